// round 3
// baseline (speedup 1.0000x reference)
#include <cuda_runtime.h>
#include <cstdint>
#include <math.h>

#define B_  16
#define S_  4096
#define D_  512
#define DH_ 256
#define M_  (B_ * S_)   // 65536
#define CL_ 128         // GARCH chunk length == BM
#define NC_ 32          // chunks per series

// Scratch (device globals: allocation-free per harness rules)
__device__ float g_h[(size_t)M_ * DH_];        // 64 MB intermediate h
__device__ float g_carry[B_ * NC_ * D_];       // 1 MB chunk carry terms
__device__ float g_cvs[B_ * NC_ * D_];         // 1 MB chunk start values

// ---------------------------------------------------------------------------
// GARCH carry pass: per (b, chunk, d) scan 128 returns -> chunk carry only.
// ---------------------------------------------------------------------------
__global__ void __launch_bounds__(256) garch_carry_kernel(
    const float* __restrict__ ret,
    const float* __restrict__ pa, const float* __restrict__ pb,
    const float* __restrict__ pw)
{
    const int g = blockIdx.x;                 // 1024 blocks
    const int d = ((g & 1) << 8) + threadIdx.x;
    const int c = (g >> 1) & (NC_ - 1);
    const int b = g >> 6;
    const float alpha = pa[0], beta = pb[0], omega = pw[0];

    const float* rp = ret + ((size_t)b * S_ + (size_t)c * CL_) * D_ + d;
    float p = 0.f;
#pragma unroll 8
    for (int k = 0; k < CL_; ++k) {
        float r = rp[(size_t)k * D_];
        p = fmaf(beta, p, fmaf(alpha, r * r, omega));
    }
    g_carry[(((b << 5) + c) << 9) + d] = p;   // zero-start value after full chunk
}

// ---------------------------------------------------------------------------
// GARCH scan pass: cvs[c] = beta^128 * cvs[c-1] + carry[c-1]; cvs[0]=0.01
// ---------------------------------------------------------------------------
__global__ void __launch_bounds__(256) garch_scan_kernel(
    const float* __restrict__ pb)
{
    const int t = blockIdx.x * 256 + threadIdx.x;   // 0..8191
    const int b = t >> 9;
    const int d = t & (D_ - 1);
    const float beta = pb[0];
    float A = 1.f;
#pragma unroll
    for (int i = 0; i < CL_; ++i) A *= beta;        // beta^128

    float cvs = 0.01f;
#pragma unroll 4
    for (int c = 0; c < NC_; ++c) {
        const int idx = (((b << 5) + c) << 9) + d;
        g_cvs[idx] = cvs;
        cvs = fmaf(A, cvs, g_carry[idx]);
    }
}

// ---------------------------------------------------------------------------
// TF32 tensor-core GEMM: 128x128 block tile, BK=16, 8 warps (64x32 each),
// cp.async double buffering, raw fp32->tf32 truncation (no cvt).
// EPI==1 recomputes the GARCH partial cv tile in smem from ret.
// ---------------------------------------------------------------------------
#define BM 128
#define BN 128
#define BK 16
#define ASTR 20
#define BSTR 136
#define AS_FLOATS (2 * BM * ASTR)          // 5120
#define BS_FLOATS (2 * BK * BSTR)          // 4352
#define CVSTR 129
#define CV_FLOATS (CL_ * CVSTR)            // 16512
#define SMEM1_BYTES ((AS_FLOATS + BS_FLOATS) * 4)                       // 37888
#define SMEM2_BYTES ((AS_FLOATS + BS_FLOATS + CV_FLOATS + CL_) * 4)    // 104448

__device__ __forceinline__ void cp_async16(void* dst_smem, const void* src_g) {
    uint32_t d32 = (uint32_t)__cvta_generic_to_shared(dst_smem);
    asm volatile("cp.async.cg.shared.global [%0], [%1], 16;" :: "r"(d32), "l"(src_g));
}

__device__ __forceinline__ float softplus_f(float z) {
    return fmaxf(z, 0.f) + log1pf(expf(-fabsf(z)));
}

template <int EPI>
__global__ void __launch_bounds__(256, 2) gemm_kernel(
    const float* __restrict__ A, const float* __restrict__ Bw,
    const float* __restrict__ bias,
    const float* __restrict__ ret,      // EPI==1 only
    const float* __restrict__ CVS,      // EPI==1 only
    const float* __restrict__ pa, const float* __restrict__ pb,
    const float* __restrict__ pw,
    float* __restrict__ C, const int N, const int K)
{
    extern __shared__ float sm[];
    float* As  = sm;                               // [2][BM][ASTR]
    float* Bs  = sm + AS_FLOATS;                   // [2][BK][BSTR]
    float* cvs_sm = sm + AS_FLOATS + BS_FLOATS;    // [CL_][CVSTR]  (EPI==1)
    float* bp     = cvs_sm + CV_FLOATS;            // [CL_]         (EPI==1)

    const int tid  = threadIdx.x;
    const int lane = tid & 31;
    const int warp = tid >> 5;
    const int wm   = (warp >> 2) * 64;   // 2x4 warp grid, 64x32 per warp
    const int wn   = (warp & 3) * 32;
    const int gid  = lane >> 2;
    const int tig  = lane & 3;
    const int bm0  = blockIdx.y * BM;
    const int bn0  = blockIdx.x * BN;

    float acc[4][4][4];
#pragma unroll
    for (int mt = 0; mt < 4; ++mt)
#pragma unroll
        for (int nt = 0; nt < 4; ++nt)
#pragma unroll
            for (int i = 0; i < 4; ++i) acc[mt][nt][i] = 0.f;

    auto load_tiles = [&](int kt, int buf) {
        const float* Ag = A + (size_t)bm0 * K + kt * BK;
#pragma unroll
        for (int i = 0; i < 2; ++i) {
            int idx = tid + i * 256;
            int r = idx >> 2, cq = (idx & 3) * 4;
            cp_async16(&As[buf * (BM * ASTR) + r * ASTR + cq],
                       Ag + (size_t)r * K + cq);
        }
        const float* Bg = Bw + (size_t)(kt * BK) * N + bn0;
#pragma unroll
        for (int i = 0; i < 2; ++i) {
            int idx = tid + i * 256;
            int r = idx >> 5, cq = (idx & 31) * 4;
            cp_async16(&Bs[buf * (BK * BSTR) + r * BSTR + cq],
                       Bg + (size_t)r * N + cq);
        }
        asm volatile("cp.async.commit_group;" ::: "memory");
    };

    const int nk = K / BK;
    load_tiles(0, 0);       // first tile in flight while we do the cv scan

    if (EPI == 1) {
        const float alpha = pa[0], beta = pb[0], omega = pw[0];
        if (tid < CL_) {
            bp[tid] = powf(beta, (float)tid);
            // zero-start partial cv scan for this block's (batch, chunk, cols)
            const float* rp = ret + (size_t)bm0 * D_ + bn0 + tid;
            float p = 0.f;
            cvs_sm[tid] = 0.f;
#pragma unroll 8
            for (int k = 1; k < CL_; ++k) {
                float r = rp[(size_t)(k - 1) * D_];
                p = fmaf(beta, p, fmaf(alpha, r * r, omega));
                cvs_sm[k * CVSTR + tid] = p;
            }
        }
    }

    for (int kt = 0; kt < nk; ++kt) {
        asm volatile("cp.async.wait_group 0;" ::: "memory");
        __syncthreads();
        const int buf = kt & 1;
        if (kt + 1 < nk) load_tiles(kt + 1, buf ^ 1);

#pragma unroll
        for (int ks = 0; ks < 2; ++ks) {
            const int k0 = ks * 8;
            uint32_t af[4][4], bf[4][2];
            const float* Ab = As + buf * (BM * ASTR);
            const float* Bb = Bs + buf * (BK * BSTR);
#pragma unroll
            for (int mt = 0; mt < 4; ++mt) {
                int r = wm + mt * 16 + gid;
                af[mt][0] = __float_as_uint(Ab[r * ASTR + k0 + tig]);
                af[mt][1] = __float_as_uint(Ab[(r + 8) * ASTR + k0 + tig]);
                af[mt][2] = __float_as_uint(Ab[r * ASTR + k0 + tig + 4]);
                af[mt][3] = __float_as_uint(Ab[(r + 8) * ASTR + k0 + tig + 4]);
            }
#pragma unroll
            for (int nt = 0; nt < 4; ++nt) {
                int c = wn + nt * 8 + gid;
                bf[nt][0] = __float_as_uint(Bb[(k0 + tig) * BSTR + c]);
                bf[nt][1] = __float_as_uint(Bb[(k0 + tig + 4) * BSTR + c]);
            }
#pragma unroll
            for (int mt = 0; mt < 4; ++mt)
#pragma unroll
                for (int nt = 0; nt < 4; ++nt)
                    asm volatile(
                        "mma.sync.aligned.m16n8k8.row.col.f32.tf32.tf32.f32 "
                        "{%0,%1,%2,%3},{%4,%5,%6,%7},{%8,%9},{%0,%1,%2,%3};"
                        : "+f"(acc[mt][nt][0]), "+f"(acc[mt][nt][1]),
                          "+f"(acc[mt][nt][2]), "+f"(acc[mt][nt][3])
                        : "r"(af[mt][0]), "r"(af[mt][1]),
                          "r"(af[mt][2]), "r"(af[mt][3]),
                          "r"(bf[nt][0]), "r"(bf[nt][1]));
        }
    }

    // Epilogue
    size_t cvsbase = 0;
    if (EPI == 1) {
        const int b = bm0 >> 12;
        const int chunk = (bm0 >> 7) & (NC_ - 1);
        cvsbase = (size_t)(((b << 5) + chunk) << 9);
    }
#pragma unroll
    for (int mt = 0; mt < 4; ++mt) {
#pragma unroll
        for (int i = 0; i < 2; ++i) {
            const int rl  = wm + mt * 16 + gid + i * 8;   // local row 0..127
            const int row = bm0 + rl;
            float bpk = (EPI == 1) ? bp[rl] : 0.f;
#pragma unroll
            for (int nt = 0; nt < 4; ++nt) {
                const int col = bn0 + wn + nt * 8 + 2 * tig;
                float v0 = acc[mt][nt][2 * i + 0] + bias[col];
                float v1 = acc[mt][nt][2 * i + 1] + bias[col + 1];
                if (EPI == 0) {
                    v0 = fmaxf(v0, 0.f);
                    v1 = fmaxf(v1, 0.f);
                } else {
                    const int cl = col - bn0;
                    float cv0 = cvs_sm[rl * CVSTR + cl]     + bpk * CVS[cvsbase + col];
                    float cv1 = cvs_sm[rl * CVSTR + cl + 1] + bpk * CVS[cvsbase + col + 1];
                    v0 = softplus_f(v0) * cv0;
                    v1 = softplus_f(v1) * cv1;
                }
                *(float2*)(C + (size_t)row * N + col) = make_float2(v0, v1);
            }
        }
    }
}

// ---------------------------------------------------------------------------
extern "C" void kernel_launch(void* const* d_in, const int* in_sizes, int n_in,
                              void* d_out, int out_size)
{
    const float* x   = (const float*)d_in[0];
    const float* ret = (const float*)d_in[1];
    const float* al  = (const float*)d_in[2];
    const float* be  = (const float*)d_in[3];
    const float* om  = (const float*)d_in[4];
    const float* W1  = (const float*)d_in[5];
    const float* b1  = (const float*)d_in[6];
    const float* W2  = (const float*)d_in[7];
    const float* b2  = (const float*)d_in[8];
    float* out = (float*)d_out;

    float* h = nullptr;
    float* cvsp = nullptr;
    cudaGetSymbolAddress((void**)&h, g_h);
    cudaGetSymbolAddress((void**)&cvsp, g_cvs);

    cudaFuncSetAttribute(gemm_kernel<1>,
                         cudaFuncAttributeMaxDynamicSharedMemorySize, SMEM2_BYTES);

    garch_carry_kernel<<<B_ * NC_ * (D_ / 256), 256>>>(ret, al, be, om);
    garch_scan_kernel<<<(B_ * D_) / 256, 256>>>(be);
    gemm_kernel<0><<<dim3(DH_ / BN, M_ / BM), 256, SMEM1_BYTES>>>(
        x, W1, b1, nullptr, nullptr, nullptr, nullptr, nullptr, h, DH_, D_);
    gemm_kernel<1><<<dim3(D_ / BN, M_ / BM), 256, SMEM2_BYTES>>>(
        h, W2, b2, ret, cvsp, al, be, om, out, D_, DH_);
}

// round 5
// speedup vs baseline: 1.2632x; 1.2632x over previous
#include <cuda_runtime.h>
#include <cstdint>
#include <math.h>

#define B_  16
#define S_  4096
#define D_  512
#define DH_ 256
#define M_  (B_ * S_)   // 65536
#define CL_ 128
#define NC_ 32

// Scratch (device globals; allocation-free per harness rules)
__device__ float g_h[(size_t)M_ * DH_];        // 64 MB intermediate h
__device__ float g_cv[(size_t)M_ * D_];        // 134 MB partial cond-var
__device__ float g_carry[B_ * NC_ * D_];
__device__ float g_cvs[B_ * NC_ * D_];
__device__ float g_w1t[DH_ * D_];              // W1^T  [256,512] (n-major, k-contig)
__device__ float g_w2t[D_ * DH_];              // W2^T  [512,256]

// ===========================================================================
// helpers
// ===========================================================================
__device__ __forceinline__ uint32_t smem_u32(const void* p) {
    uint32_t a;
    asm("{ .reg .u64 t; cvta.to.shared.u64 t, %1; cvt.u32.u64 %0, t; }"
        : "=r"(a) : "l"(p));
    return a;
}

__device__ __forceinline__ void cp16(uint32_t dst, const void* src) {
    asm volatile("cp.async.cg.shared.global [%0], [%1], 16;" :: "r"(dst), "l"(src));
}
#define CP_COMMIT() asm volatile("cp.async.commit_group;" ::: "memory")
#define CP_WAIT0()  asm volatile("cp.async.wait_group 0;" ::: "memory")

#define LDSM_X4(r0, r1, r2, r3, addr) \
    asm volatile("ldmatrix.sync.aligned.m8n8.x4.shared.b16 {%0,%1,%2,%3}, [%4];" \
        : "=r"(r0), "=r"(r1), "=r"(r2), "=r"(r3) : "r"(addr))

__device__ __forceinline__ float softplus_f(float z) {
    return fmaxf(z, 0.f) + log1pf(expf(-fabsf(z)));
}

// ===========================================================================
// GARCH (proven R2 scheme)
// ===========================================================================
__global__ void __launch_bounds__(256) garch_partial_kernel(
    const float* __restrict__ ret,
    const float* __restrict__ pa, const float* __restrict__ pb,
    const float* __restrict__ pw)
{
    const int g = blockIdx.x;
    const int d = ((g & 1) << 8) + threadIdx.x;
    const int c = (g >> 1) & (NC_ - 1);
    const int b = g >> 6;
    const float alpha = pa[0], beta = pb[0], omega = pw[0];
    const size_t base = ((size_t)b * S_ + (size_t)c * CL_) * D_ + d;
    const float* rp = ret + base;
    float* cp = g_cv + base;
    float p = 0.f;
    cp[0] = 0.f;
#pragma unroll 8
    for (int k = 1; k < CL_; ++k) {
        float r = rp[(size_t)(k - 1) * D_];
        p = fmaf(beta, p, fmaf(alpha, r * r, omega));
        cp[(size_t)k * D_] = p;
    }
    float rl = rp[(size_t)(CL_ - 1) * D_];
    g_carry[(((b << 5) + c) << 9) + d] = fmaf(beta, p, fmaf(alpha, rl * rl, omega));
}

__global__ void __launch_bounds__(256) garch_scan_kernel(const float* __restrict__ pb)
{
    const int t = blockIdx.x * 256 + threadIdx.x;
    const int b = t >> 9;
    const int d = t & (D_ - 1);
    const float beta = pb[0];
    float A = 1.f;
#pragma unroll
    for (int i = 0; i < CL_; ++i) A *= beta;
    float cvs = 0.01f;
#pragma unroll 4
    for (int c = 0; c < NC_; ++c) {
        const int idx = (((b << 5) + c) << 9) + d;
        g_cvs[idx] = cvs;
        cvs = fmaf(A, cvs, g_carry[idx]);
    }
}

// ===========================================================================
// Weight transpose [K,N] -> [N,K]
// ===========================================================================
__global__ void transpose_kernel(const float* __restrict__ src, float* __restrict__ dst,
                                 int K, int N)
{
    __shared__ float t[32][33];
    const int kb = blockIdx.x * 32, nb = blockIdx.y * 32;
    for (int i = threadIdx.y; i < 32; i += 8)
        t[i][threadIdx.x] = src[(size_t)(kb + i) * N + nb + threadIdx.x];
    __syncthreads();
    for (int i = threadIdx.y; i < 32; i += 8)
        dst[(size_t)(nb + i) * K + kb + threadIdx.x] = t[threadIdx.x][i];
}

// ===========================================================================
// TF32 mma.sync GEMM with ldmatrix fragment feed.
// 128x128 block tile, BK=32, 8 warps (64x32 each), 2-stage cp.async ring.
// A [m][K] k-contig, Bt [n][K] k-contig. Smem rows: 128B data + 16B pad.
// ===========================================================================
#define BK 32
#define ROWB 144                          // smem row stride in bytes
#define TILE_BYTES (128 * ROWB)           // 18432
#define STAGE_BYTES (2 * TILE_BYTES)      // 36864 (A + B)
#define SMEM_BYTES (2 * STAGE_BYTES)      // 73728 (2 stages)

template <int EPI>
__global__ void __launch_bounds__(256, 2) gemm_tc(
    const float* __restrict__ A, const float* __restrict__ Bt,
    const float* __restrict__ bias,
    const float* __restrict__ CV, const float* __restrict__ CVS,
    const float* __restrict__ pbeta,
    float* __restrict__ C, const int N, const int K)
{
    extern __shared__ char smraw[];
    const uint32_t sbase = smem_u32(smraw);
    __shared__ float bias_sm[128];
    __shared__ float bp_sm[CL_];

    const int tid  = threadIdx.x;
    const int lane = tid & 31;
    const int warp = tid >> 5;
    const int wm   = (warp >> 2) * 64;    // 2x4 warp grid, 64x32 per warp
    const int wn   = (warp & 3) * 32;
    const int gid  = lane >> 2;
    const int tig  = lane & 3;
    const int bm0  = blockIdx.y * 128;
    const int bn0  = blockIdx.x * 128;
    const int nk   = K / BK;

    if (tid < 128) bias_sm[tid] = bias[bn0 + tid];
    if (EPI == 1 && tid >= 128) bp_sm[tid - 128] = powf(pbeta[0], (float)(tid - 128));

    float acc[4][4][4];
#pragma unroll
    for (int mt = 0; mt < 4; ++mt)
#pragma unroll
        for (int nt = 0; nt < 4; ++nt)
#pragma unroll
            for (int i = 0; i < 4; ++i) acc[mt][nt][i] = 0.f;

    auto load_stage = [&](int kt, int st) {
        const uint32_t tb = sbase + st * STAGE_BYTES;
#pragma unroll
        for (int i = 0; i < 4; ++i) {
            const int id = tid + i * 256;          // 1024 chunks of 16B
            const int r = id >> 3, s = id & 7;
            cp16(tb + r * ROWB + s * 16,
                 A + (size_t)(bm0 + r) * K + kt * BK + s * 4);
        }
#pragma unroll
        for (int i = 0; i < 4; ++i) {
            const int id = tid + i * 256;
            const int r = id >> 3, s = id & 7;
            cp16(tb + TILE_BYTES + r * ROWB + s * 16,
                 Bt + (size_t)(bn0 + r) * K + kt * BK + s * 4);
        }
        CP_COMMIT();
    };

    // ldmatrix per-lane source offsets
    const int half = lane >> 3;
    const uint32_t laneA = (uint32_t)((wm + (lane & 7) + (half & 1) * 8) * ROWB
                                      + (half >> 1) * 16);
    const uint32_t laneB = (uint32_t)((wn + (lane & 7)) * ROWB + (lane >> 3) * 16);

    load_stage(0, 0);

    for (int kt = 0; kt < nk; ++kt) {
        CP_WAIT0();
        __syncthreads();
        const uint32_t aB = sbase + (kt & 1) * STAGE_BYTES;
        const uint32_t bB = aB + TILE_BYTES;
        if (kt + 1 < nk) load_stage(kt + 1, (kt + 1) & 1);

#pragma unroll
        for (int qp = 0; qp < 2; ++qp) {           // pairs of k8 steps
            uint32_t bf[4][4];
#pragma unroll
            for (int nt = 0; nt < 4; ++nt)
                LDSM_X4(bf[nt][0], bf[nt][1], bf[nt][2], bf[nt][3],
                        bB + laneB + nt * (8 * ROWB) + qp * 64);
#pragma unroll
            for (int q2 = 0; q2 < 2; ++q2) {
                const int q = 2 * qp + q2;
                uint32_t af[4][4];
#pragma unroll
                for (int mt = 0; mt < 4; ++mt)
                    LDSM_X4(af[mt][0], af[mt][1], af[mt][2], af[mt][3],
                            aB + laneA + mt * (16 * ROWB) + q * 32);
#pragma unroll
                for (int mt = 0; mt < 4; ++mt)
#pragma unroll
                    for (int nt = 0; nt < 4; ++nt)
                        asm volatile(
                            "mma.sync.aligned.m16n8k8.row.col.f32.tf32.tf32.f32 "
                            "{%0,%1,%2,%3},{%4,%5,%6,%7},{%8,%9},{%0,%1,%2,%3};"
                            : "+f"(acc[mt][nt][0]), "+f"(acc[mt][nt][1]),
                              "+f"(acc[mt][nt][2]), "+f"(acc[mt][nt][3])
                            : "r"(af[mt][0]), "r"(af[mt][1]),
                              "r"(af[mt][2]), "r"(af[mt][3]),
                              "r"(bf[nt][2 * q2]), "r"(bf[nt][2 * q2 + 1]));
            }
        }
    }

    // Epilogue (R2 scheme)
    size_t cvsbase = 0;
    if (EPI == 1) {
        const int b = bm0 >> 12;
        const int chunk = (bm0 >> 7) & (NC_ - 1);
        cvsbase = (size_t)(((b << 5) + chunk) << 9);
    }
#pragma unroll
    for (int mt = 0; mt < 4; ++mt) {
#pragma unroll
        for (int i = 0; i < 2; ++i) {
            const int rl  = wm + mt * 16 + gid + i * 8;
            const int row = bm0 + rl;
            const float bpk = (EPI == 1) ? bp_sm[rl & (CL_ - 1)] : 0.f;
#pragma unroll
            for (int nt = 0; nt < 4; ++nt) {
                const int col = bn0 + wn + nt * 8 + 2 * tig;
                float v0 = acc[mt][nt][2 * i + 0] + bias_sm[col - bn0];
                float v1 = acc[mt][nt][2 * i + 1] + bias_sm[col - bn0 + 1];
                if (EPI == 0) {
                    v0 = fmaxf(v0, 0.f);
                    v1 = fmaxf(v1, 0.f);
                } else {
                    float cv0 = CV[(size_t)row * N + col]     + bpk * CVS[cvsbase + col];
                    float cv1 = CV[(size_t)row * N + col + 1] + bpk * CVS[cvsbase + col + 1];
                    v0 = softplus_f(v0) * cv0;
                    v1 = softplus_f(v1) * cv1;
                }
                *(float2*)(C + (size_t)row * N + col) = make_float2(v0, v1);
            }
        }
    }
}

// ===========================================================================
extern "C" void kernel_launch(void* const* d_in, const int* in_sizes, int n_in,
                              void* d_out, int out_size)
{
    const float* x   = (const float*)d_in[0];
    const float* ret = (const float*)d_in[1];
    const float* al  = (const float*)d_in[2];
    const float* be  = (const float*)d_in[3];
    const float* om  = (const float*)d_in[4];
    const float* W1  = (const float*)d_in[5];
    const float* b1  = (const float*)d_in[6];
    const float* W2  = (const float*)d_in[7];
    const float* b2  = (const float*)d_in[8];
    float* out = (float*)d_out;

    float *h, *cv, *cvs, *w1t, *w2t;
    cudaGetSymbolAddress((void**)&h,   g_h);
    cudaGetSymbolAddress((void**)&cv,  g_cv);
    cudaGetSymbolAddress((void**)&cvs, g_cvs);
    cudaGetSymbolAddress((void**)&w1t, g_w1t);
    cudaGetSymbolAddress((void**)&w2t, g_w2t);

    cudaFuncSetAttribute(gemm_tc<0>, cudaFuncAttributeMaxDynamicSharedMemorySize, SMEM_BYTES);
    cudaFuncSetAttribute(gemm_tc<1>, cudaFuncAttributeMaxDynamicSharedMemorySize, SMEM_BYTES);

    transpose_kernel<<<dim3(D_ / 32, DH_ / 32), dim3(32, 8)>>>(W1, w1t, D_, DH_);
    transpose_kernel<<<dim3(DH_ / 32, D_ / 32), dim3(32, 8)>>>(W2, w2t, DH_, D_);
    garch_partial_kernel<<<B_ * NC_ * (D_ / 256), 256>>>(ret, al, be, om);
    garch_scan_kernel<<<(B_ * D_) / 256, 256>>>(be);
    gemm_tc<0><<<dim3(DH_ / 128, M_ / 128), 256, SMEM_BYTES>>>(
        x, w1t, b1, nullptr, nullptr, nullptr, h, DH_, D_);
    gemm_tc<1><<<dim3(D_ / 128, M_ / 128), 256, SMEM_BYTES>>>(
        h, w2t, b2, cv, cvs, be, out, D_, DH_);
}